// round 8
// baseline (speedup 1.0000x reference)
#include <cuda_runtime.h>

#define BB 4
#define QQ 256
#define VV 2048
#define HH 512
#define UU 128

typedef unsigned int       u32;
typedef unsigned long long u64;
typedef unsigned short     u16;

// Scratch (device globals: allocation-free rule)
__device__ float g_pq[BB * QQ * UU];          // [B,Q,U] fp32
__device__ float g_pv[BB * VV * UU];          // [B,V,U] fp32
__device__ u16   g_ahi[BB * QQ * VV];         // attn hi bf16 [B,Q,V]
__device__ u16   g_alo[BB * QQ * VV];         // attn lo bf16
__device__ u16   g_vthi[BB * HH * VV];        // values^T hi bf16 [B,H,V]
__device__ u16   g_vtlo[BB * HH * VV];        // values^T lo bf16
__device__ u16   g_w1thi[UU * HH];            // w1^T hi bf16 [U,H]
__device__ u16   g_w1tlo[UU * HH];
__device__ u16   g_w2thi[UU * HH];            // w2^T hi bf16 [U,H]
__device__ u16   g_w2tlo[UU * HH];

__device__ __forceinline__ float ftanh(float x) {
    float y; asm("tanh.approx.f32 %0, %1;" : "=f"(y) : "f"(x)); return y;
}
__device__ __forceinline__ u16 f2bf(float x) {
    u16 u; asm("cvt.rn.bf16.f32 %0, %1;" : "=h"(u) : "f"(x)); return u;
}
__device__ __forceinline__ float bf2f(u16 u) {
    float f; asm("cvt.f32.bf16 %0, %1;" : "=f"(f) : "h"(u)); return f;
}
__device__ __forceinline__ u32 smem_u32(const void* p) {
    u32 a;
    asm("{ .reg .u64 t; cvta.to.shared.u64 t, %1; cvt.u32.u64 %0, t; }"
        : "=r"(a) : "l"(p));
    return a;
}
__device__ __forceinline__ void ldsm4(u32& r0, u32& r1, u32& r2, u32& r3, u32 a) {
    asm volatile("ldmatrix.sync.aligned.m8n8.x4.shared.b16 {%0,%1,%2,%3}, [%4];"
                 : "=r"(r0), "=r"(r1), "=r"(r2), "=r"(r3) : "r"(a));
}
__device__ __forceinline__ void ldsm2(u32& r0, u32& r1, u32 a) {
    asm volatile("ldmatrix.sync.aligned.m8n8.x2.shared.b16 {%0,%1}, [%2];"
                 : "=r"(r0), "=r"(r1) : "r"(a));
}
__device__ __forceinline__ void mma16816(float* d, const u32* a, const u32* b) {
    asm volatile(
        "mma.sync.aligned.m16n8k16.row.col.f32.bf16.bf16.f32 "
        "{%0,%1,%2,%3}, {%4,%5,%6,%7}, {%8,%9}, {%0,%1,%2,%3};"
        : "+f"(d[0]), "+f"(d[1]), "+f"(d[2]), "+f"(d[3])
        : "r"(a[0]), "r"(a[1]), "r"(a[2]), "r"(a[3]), "r"(b[0]), "r"(b[1]));
}
__device__ __forceinline__ void pack2(float a, float b, u32& h, u32& l) {
    u16 ha = f2bf(a), hb = f2bf(b);
    u16 la = f2bf(a - bf2f(ha)), lb = f2bf(b - bf2f(hb));
    h = (u32)ha | ((u32)hb << 16);
    l = (u32)la | ((u32)lb << 16);
}

// ---------------------------------------------------------------------------
// Kernel 0: w1/w2 transpose + bf16 hi/lo. 32 blocks (tiny, before proj).
// ---------------------------------------------------------------------------
__global__ __launch_bounds__(256) void wconv_kernel(
    const float* __restrict__ w1, const float* __restrict__ w2)
{
    __shared__ float ts[64 * 65];
    const int wb = blockIdx.x, tid = threadIdx.x;
    const float* W = (wb < 16) ? w1 : w2;
    u16* dh = (wb < 16) ? g_w1thi : g_w2thi;
    u16* dl = (wb < 16) ? g_w1tlo : g_w2tlo;
    const int t = wb & 15;
    const int h0 = (t & 7) * 64, u0 = (t >> 3) * 64;
    const int r = tid >> 2, c0 = tid & 3;
#pragma unroll
    for (int it = 0; it < 4; it++) {
        int c4 = c0 * 4 + it;
        float4 f = ((const float4*)(W + (size_t)(h0 + r) * UU + u0))[c4];
        ts[r * 65 + c4 * 4 + 0] = f.x;
        ts[r * 65 + c4 * 4 + 1] = f.y;
        ts[r * 65 + c4 * 4 + 2] = f.z;
        ts[r * 65 + c4 * 4 + 3] = f.w;
    }
    __syncthreads();
    const int ur = tid >> 2, s0 = tid & 3;
#pragma unroll
    for (int it = 0; it < 4; it++) {
        int hs = s0 * 4 + it;
        float f0 = ts[(hs * 4 + 0) * 65 + ur];
        float f1 = ts[(hs * 4 + 1) * 65 + ur];
        float f2 = ts[(hs * 4 + 2) * 65 + ur];
        float f3 = ts[(hs * 4 + 3) * 65 + ur];
        u32 h01, l01, h23, l23;
        pack2(f0, f1, h01, l01);
        pack2(f2, f3, h23, l23);
        size_t off = (size_t)(u0 + ur) * HH + h0 + hs * 4;
        *(uint2*)(dh + off) = make_uint2(h01, h23);
        *(uint2*)(dl + off) = make_uint2(l01, l23);
    }
}

// ---------------------------------------------------------------------------
// Kernel A: projections via mma.sync bf16 hi/lo. Static SMEM, R6 skeleton
// (store -> prefetch -> sync -> compute -> sync). A (values/queries) loaded
// fp32 and converted inline; B = w^T hi/lo pre-converted.
// CTA tile M=64 x N=128(=U), BK=64, 8 chunks. 8 warps = 2(m)x4(n).
// ---------------------------------------------------------------------------
__global__ __launch_bounds__(256) void proj_tc_kernel(
    const float* __restrict__ queries, const float* __restrict__ values)
{
    __shared__ __align__(16) u16 sAh[64 * 72];
    __shared__ __align__(16) u16 sAl[64 * 72];
    __shared__ __align__(16) u16 sBh[128 * 72];
    __shared__ __align__(16) u16 sBl[128 * 72];

    const int tid = threadIdx.x;
    const int wid = tid >> 5;
    const int lane = tid & 31;
    const int bx = blockIdx.x;

    const float* Afp; const u16 *Bh, *Bl; float* C; int m0;
    if (bx < 128) { Afp = values;  Bh = g_w2thi; Bl = g_w2tlo; C = g_pv; m0 = bx * 64; }
    else          { Afp = queries; Bh = g_w1thi; Bl = g_w1tlo; C = g_pq; m0 = (bx - 128) * 64; }

    const int wm0 = (wid >> 2) * 32;   // 0,32
    const int wn0 = (wid & 3) * 32;    // 0,32,64,96

    const int ar = tid >> 2, ac4 = tid & 3;   // A: row, 4 float4 (16 floats)
    const int br = tid >> 1, bg = tid & 1;    // B: row, 4 granules

    const float4* gA4 = (const float4*)(Afp + (size_t)m0 * HH);
    const uint4* gBh4 = (const uint4*)Bh;
    const uint4* gBl4 = (const uint4*)Bl;
    const int RWA = HH / 4;   // 128
    const int RWB = HH / 8;   // 64

    float dacc[2][4][4];
#pragma unroll
    for (int i = 0; i < 2; i++)
#pragma unroll
        for (int j = 0; j < 4; j++)
#pragma unroll
            for (int c = 0; c < 4; c++) dacc[i][j][c] = 0.f;

    float4 pA[4];
    uint4 pBh[4], pBl[4];
#pragma unroll
    for (int it = 0; it < 4; it++)
        pA[it] = gA4[(size_t)ar * RWA + ac4 * 4 + it];
#pragma unroll
    for (int j = 0; j < 4; j++) {
        pBh[j] = gBh4[(size_t)br * RWB + bg * 4 + j];
        pBl[j] = gBl4[(size_t)br * RWB + bg * 4 + j];
    }

    const u32 bAh = smem_u32(sAh), bAl = smem_u32(sAl);
    const u32 bBh = smem_u32(sBh), bBl = smem_u32(sBl);

    const int arow = wm0 + (lane & 15);
    const u32 aoff = (u32)(arow * 9 + (lane >> 4)) * 16;
    const int brow = wn0 + (lane & 7);
    const u32 boff = (u32)(brow * 9 + ((lane >> 3) & 1)) * 16;

    const int NCH = HH / 64;   // 8

    for (int c = 0; c < NCH; c++) {
        // store chunk c (A converted inline)
#pragma unroll
        for (int it = 0; it < 4; it++) {
            u32 h01, l01, h23, l23;
            pack2(pA[it].x, pA[it].y, h01, l01);
            pack2(pA[it].z, pA[it].w, h23, l23);
            u32 s = (u32)(ar * 72 + (ac4 * 4 + it) * 4);
            *(uint2*)(sAh + s) = make_uint2(h01, h23);
            *(uint2*)(sAl + s) = make_uint2(l01, l23);
        }
#pragma unroll
        for (int j = 0; j < 4; j++) {
            u32 s = (u32)(br * 72 + (bg * 4 + j) * 8);
            *(uint4*)(sBh + s) = pBh[j];
            *(uint4*)(sBl + s) = pBl[j];
        }
        // prefetch chunk c+1 (lands during compute)
        if (c + 1 < NCH) {
            int fa = (c + 1) * 16, fb = (c + 1) * 8;
#pragma unroll
            for (int it = 0; it < 4; it++)
                pA[it] = gA4[(size_t)ar * RWA + fa + ac4 * 4 + it];
#pragma unroll
            for (int j = 0; j < 4; j++) {
                pBh[j] = gBh4[(size_t)br * RWB + fb + bg * 4 + j];
                pBl[j] = gBl4[(size_t)br * RWB + fb + bg * 4 + j];
            }
        }
        __syncthreads();

#pragma unroll
        for (int kb = 0; kb < 4; kb++) {
            u32 kadd = (u32)(kb * 2) * 16;
            u32 ah[2][4], al[2][4], bh[4][2], bl[4][2];
#pragma unroll
            for (int mf = 0; mf < 2; mf++) {
                u32 ad = (u32)(mf * 16 * 9) * 16 + aoff + kadd;
                ldsm4(ah[mf][0], ah[mf][1], ah[mf][2], ah[mf][3], bAh + ad);
                ldsm4(al[mf][0], al[mf][1], al[mf][2], al[mf][3], bAl + ad);
            }
#pragma unroll
            for (int nf = 0; nf < 4; nf++) {
                u32 bd = (u32)(nf * 8 * 9) * 16 + boff + kadd;
                ldsm2(bh[nf][0], bh[nf][1], bBh + bd);
                ldsm2(bl[nf][0], bl[nf][1], bBl + bd);
            }
            // product-outer order: dependency spacing 8 per accumulator
#pragma unroll
            for (int mf = 0; mf < 2; mf++)
#pragma unroll
                for (int nf = 0; nf < 4; nf++)
                    mma16816(dacc[mf][nf], ah[mf], bh[nf]);
#pragma unroll
            for (int mf = 0; mf < 2; mf++)
#pragma unroll
                for (int nf = 0; nf < 4; nf++)
                    mma16816(dacc[mf][nf], ah[mf], bl[nf]);
#pragma unroll
            for (int mf = 0; mf < 2; mf++)
#pragma unroll
                for (int nf = 0; nf < 4; nf++)
                    mma16816(dacc[mf][nf], al[mf], bh[nf]);
        }
        __syncthreads();
    }

    const int g = lane >> 2;
    const int t = lane & 3;
#pragma unroll
    for (int mf = 0; mf < 2; mf++)
#pragma unroll
        for (int nf = 0; nf < 4; nf++) {
            int row = m0 + wm0 + mf * 16 + g;
            int col = wn0 + nf * 8 + t * 2;
            float2 v0, v1;
            v0.x = dacc[mf][nf][0]; v0.y = dacc[mf][nf][1];
            v1.x = dacc[mf][nf][2]; v1.y = dacc[mf][nf][3];
            *(float2*)(C + (size_t)row * UU + col) = v0;
            *(float2*)(C + (size_t)(row + 8) * UU + col) = v1;
        }
}

// ---------------------------------------------------------------------------
// Kernel B: FUSED: blocks [0,148) = scores+softmax (persistent, MUFU-bound);
// blocks [148,1172) = values^T bf16 hi/lo conversion (memory-bound, hides
// under score's MUFU time via SM co-residency).
// ---------------------------------------------------------------------------
#define SCORE_GRID 148
#define CPB 37
#define NQMAX 7

__global__ __launch_bounds__(256) void score_fused_kernel(
    const float* __restrict__ vvec, const float* __restrict__ values)
{
    __shared__ float ts[64 * 65];             // used by convert branch only
    extern __shared__ float4 sm4[];

    const int tid = threadIdx.x;

    if (blockIdx.x >= SCORE_GRID) {
        // ---- values^T conversion branch ----
        const int vb = blockIdx.x - SCORE_GRID;       // 0..1023
        const int b = vb >> 8, t = vb & 255;
        const int v0 = (t & 31) * 64, h0 = (t >> 5) * 64;
        const int r = tid >> 2, c0 = tid & 3;
#pragma unroll
        for (int it = 0; it < 4; it++) {
            int c4 = c0 * 4 + it;
            float4 f = ((const float4*)(values + (size_t)(b * VV + v0 + r) * HH + h0))[c4];
            ts[r * 65 + c4 * 4 + 0] = f.x;
            ts[r * 65 + c4 * 4 + 1] = f.y;
            ts[r * 65 + c4 * 4 + 2] = f.z;
            ts[r * 65 + c4 * 4 + 3] = f.w;
        }
        __syncthreads();
        const int hr = tid >> 2, s0 = tid & 3;
#pragma unroll
        for (int it = 0; it < 4; it++) {
            int vs = s0 * 4 + it;
            float f0 = ts[(vs * 4 + 0) * 65 + hr];
            float f1 = ts[(vs * 4 + 1) * 65 + hr];
            float f2 = ts[(vs * 4 + 2) * 65 + hr];
            float f3 = ts[(vs * 4 + 3) * 65 + hr];
            u32 h01, l01, h23, l23;
            pack2(f0, f1, h01, l01);
            pack2(f2, f3, h23, l23);
            size_t off = (size_t)(b * HH + h0 + hr) * VV + v0 + vs * 4;
            *(uint2*)(g_vthi + off) = make_uint2(h01, h23);
            *(uint2*)(g_vtlo + off) = make_uint2(l01, l23);
        }
        return;
    }

    // ---- score branch ----
    float4* pvs4 = sm4;                       // 32*33 f4
    float4* pqs4 = sm4 + 1056;                // 224 f4
    float4* vs4  = sm4 + 1056 + 224;          // 32 f4
    float*  scores = (float*)(sm4 + 1312);    // 7*2048 floats
    float*  sp     = scores + NQMAX * VV;     // 1792 floats

    const int b     = blockIdx.x / CPB;
    const int local = blockIdx.x % CPB;
    const int nq = (local < 34) ? 7 : 6;
    const int q0 = (local < 34) ? local * 7 : 238 + (local - 34) * 6;

    {
        const float4* pqg4 = (const float4*)(g_pq + (size_t)(b * QQ + q0) * UU);
        if (tid < nq * 32) pqs4[tid] = pqg4[tid];
        if (tid < 32) vs4[tid] = ((const float4*)vvec)[tid];
    }

    const float4* pv4 = (const float4*)g_pv;
    const int r  = tid & 31;
    const int ug = tid >> 5;
    const int lrr = tid >> 5;
    const int lc  = tid & 31;

    float4 pf[4];
#pragma unroll
    for (int i = 0; i < 4; i++)
        pf[i] = pv4[(size_t)(b * VV + lrr + i * 8) * 32 + lc];

    __syncthreads();

    float4 vw[4];
#pragma unroll
    for (int u4 = 0; u4 < 4; u4++) vw[u4] = vs4[ug * 4 + u4];

    for (int vt = 0; vt < VV; vt += 32) {
#pragma unroll
        for (int i = 0; i < 4; i++)
            pvs4[(lrr + i * 8) * 33 + lc] = pf[i];
        if (vt + 32 < VV) {
#pragma unroll
            for (int i = 0; i < 4; i++)
                pf[i] = pv4[(size_t)(b * VV + vt + 32 + lrr + i * 8) * 32 + lc];
        }
        __syncthreads();

        float acc[NQMAX];
#pragma unroll
        for (int q = 0; q < NQMAX; q++) acc[q] = 0.f;

        const float4* prow = pvs4 + r * 33 + ug * 4;
#pragma unroll
        for (int u4 = 0; u4 < 4; u4++) {
            float4 p = prow[u4];
            float4 w = vw[u4];
#pragma unroll
            for (int q = 0; q < NQMAX; q++) {
                float4 qv = pqs4[q * 32 + ug * 4 + u4];
                acc[q] += ftanh(qv.x + p.x) * w.x;
                acc[q] += ftanh(qv.y + p.y) * w.y;
                acc[q] += ftanh(qv.z + p.z) * w.z;
                acc[q] += ftanh(qv.w + p.w) * w.w;
            }
        }
#pragma unroll
        for (int q = 0; q < NQMAX; q++) sp[q * 256 + tid] = acc[q];
        __syncthreads();

        if (tid < 224) {
            int q = tid >> 5, rr = tid & 31;
            float s = 0.f;
#pragma unroll
            for (int u = 0; u < 8; u++) s += sp[q * 256 + u * 32 + rr];
            scores[q * VV + vt + rr] = s;
        }
        __syncthreads();
    }

    float* red = sp;
    for (int qi = 0; qi < nq; qi++) {
        float* sc = scores + qi * VV;

        float m = -1e30f;
        for (int i = tid; i < VV; i += 256) m = fmaxf(m, sc[i]);
        red[tid] = m;
        __syncthreads();
        for (int s = 128; s > 0; s >>= 1) {
            if (tid < s) red[tid] = fmaxf(red[tid], red[tid + s]);
            __syncthreads();
        }
        m = red[0];
        __syncthreads();

        float lsum = 0.f;
        for (int i = tid; i < VV; i += 256) {
            float e = __expf(sc[i] - m);
            sc[i] = e;
            lsum += e;
        }
        red[tid] = lsum;
        __syncthreads();
        for (int s = 128; s > 0; s >>= 1) {
            if (tid < s) red[tid] += red[tid + s];
            __syncthreads();
        }
        float inv = 1.f / red[0];
        __syncthreads();

        size_t rowoff = (size_t)(b * QQ + q0 + qi) * VV;
        const float4* sc4 = (const float4*)sc;
        for (int i = tid; i < VV / 4; i += 256) {
            float4 e = sc4[i];
            float f0 = e.x * inv, f1 = e.y * inv, f2 = e.z * inv, f3 = e.w * inv;
            u32 h01, l01, h23, l23;
            pack2(f0, f1, h01, l01);
            pack2(f2, f3, h23, l23);
            *(uint2*)(g_ahi + rowoff + i * 4) = make_uint2(h01, h23);
            *(uint2*)(g_alo + rowoff + i * 4) = make_uint2(l01, l23);
        }
        __syncthreads();
    }
}

// ---------------------------------------------------------------------------
// Kernel C: out[b] = attn[b] @ values[b] via mma.sync bf16 hi/lo.
// CTA tile M=64 x N=32, BK=64, 32 chunks. 8 warps = 4(m)x2(n), warp 16x16.
// Grid (16, 4, 4) = 256 CTAs, 27.6KB SMEM -> 2 CTAs/SM. Separate
// accumulators per product (independent HMMA chains).
// ---------------------------------------------------------------------------
__global__ __launch_bounds__(256) void av_mma_kernel(float* __restrict__ out)
{
    __shared__ __align__(16) u16 sAh[64 * 72];
    __shared__ __align__(16) u16 sAl[64 * 72];
    __shared__ __align__(16) u16 sBh[32 * 72];
    __shared__ __align__(16) u16 sBl[32 * 72];

    const int tid = threadIdx.x;
    const int wid = tid >> 5;
    const int lane = tid & 31;

    const int b  = blockIdx.z;
    const int m0 = blockIdx.y * 64;
    const int n0 = blockIdx.x * 32;

    const int wm0 = (wid >> 1) * 16;   // 0,16,32,48
    const int wn0 = (wid & 1) * 16;    // 0,16

    // global load coords: A 64 rows x 8 granules (2/thread), B 32x8 (1/thread)
    const int ar = tid >> 2, ag = (tid & 3) * 2;
    const int br = tid >> 3, bgi = tid & 7;

    const uint4* gAh = (const uint4*)(g_ahi + (size_t)(b * QQ + m0) * VV);
    const uint4* gAl = (const uint4*)(g_alo + (size_t)(b * QQ + m0) * VV);
    const uint4* gBh = (const uint4*)(g_vthi + (size_t)(b * HH + n0) * VV);
    const uint4* gBl = (const uint4*)(g_vtlo + (size_t)(b * HH + n0) * VV);
    const int RW = VV / 8;    // 256 granules per row

    // accP[product][nf][4]: hh, hl, lh
    float accP[3][2][4];
#pragma unroll
    for (int p = 0; p < 3; p++)
#pragma unroll
        for (int j = 0; j < 2; j++)
#pragma unroll
            for (int c = 0; c < 4; c++) accP[p][j][c] = 0.f;

    uint4 pAh[2], pAl[2], pBh, pBl;
#pragma unroll
    for (int j = 0; j < 2; j++) {
        pAh[j] = gAh[(size_t)ar * RW + ag + j];
        pAl[j] = gAl[(size_t)ar * RW + ag + j];
    }
    pBh = gBh[(size_t)br * RW + bgi];
    pBl = gBl[(size_t)br * RW + bgi];

    const u32 bAh = smem_u32(sAh), bAl = smem_u32(sAl);
    const u32 bBh = smem_u32(sBh), bBl = smem_u32(sBl);

    // ldmatrix addressing
    const int arow = wm0 + (lane & 15);
    const u32 aoff = (u32)(arow * 9 + (lane >> 4)) * 16;
    const int brow = wn0 + ((lane >> 4) << 3) + (lane & 7);
    const u32 boff = (u32)(brow * 9 + ((lane >> 3) & 1)) * 16;

    const int NCH = VV / 64;   // 32

    for (int c = 0; c < NCH; c++) {
        // store chunk c
#pragma unroll
        for (int j = 0; j < 2; j++) {
            u32 s = (u32)(ar * 9 + ag + j) * 8;
            *(uint4*)(sAh + s) = pAh[j];
            *(uint4*)(sAl + s) = pAl[j];
        }
        {
            u32 s = (u32)(br * 9 + bgi) * 8;
            *(uint4*)(sBh + s) = pBh;
            *(uint4*)(sBl + s) = pBl;
        }
        // prefetch chunk c+1
        if (c + 1 < NCH) {
            int g0 = (c + 1) * 8;
#pragma unroll
            for (int j = 0; j < 2; j++) {
                pAh[j] = gAh[(size_t)ar * RW + g0 + ag + j];
                pAl[j] = gAl[(size_t)ar * RW + g0 + ag + j];
            }
            pBh = gBh[(size_t)br * RW + g0 + bgi];
            pBl = gBl[(size_t)br * RW + g0 + bgi];
        }
        __syncthreads();

#pragma unroll
        for (int kb = 0; kb < 4; kb++) {
            u32 kadd = (u32)(kb * 2) * 16;
            u32 ah[4], al[4], bh[4], bl[4];
            ldsm4(ah[0], ah[1], ah[2], ah[3], bAh + aoff + kadd);
            ldsm4(al[0], al[1], al[2], al[3], bAl + aoff + kadd);
            ldsm4(bh[0], bh[1], bh[2], bh[3], bBh + boff + kadd);
            ldsm4(bl[0], bl[1], bl[2], bl[3], bBl + boff + kadd);
            // 6 independent chains (one per acc)
            mma16816(accP[0][0], ah, bh + 0);
            mma16816(accP[0][1], ah, bh + 2);
            mma16816(accP[1][0], ah, bl + 0);
            mma16816(accP[1][1], ah, bl + 2);
            mma16816(accP[2][0], al, bh + 0);
            mma16816(accP[2][1], al, bh + 2);
        }
        __syncthreads();
    }

    const int g = lane >> 2;
    const int t = lane & 3;
#pragma unroll
    for (int nf = 0; nf < 2; nf++) {
        float s0 = accP[0][nf][0] + accP[1][nf][0] + accP[2][nf][0];
        float s1 = accP[0][nf][1] + accP[1][nf][1] + accP[2][nf][1];
        float s2 = accP[0][nf][2] + accP[1][nf][2] + accP[2][nf][2];
        float s3 = accP[0][nf][3] + accP[1][nf][3] + accP[2][nf][3];
        int row = m0 + wm0 + g;
        int col = n0 + wn0 + nf * 8 + t * 2;
        *(float2*)(out + (size_t)(b * QQ + row) * HH + col) = make_float2(s0, s1);
        *(float2*)(out + (size_t)(b * QQ + row + 8) * HH + col) = make_float2(s2, s3);
    }
}

// ---------------------------------------------------------------------------
extern "C" void kernel_launch(void* const* d_in, const int* in_sizes, int n_in,
                              void* d_out, int out_size)
{
    const float* queries = (const float*)d_in[0];
    const float* values  = (const float*)d_in[1];
    const float* w1      = (const float*)d_in[2];
    const float* w2      = (const float*)d_in[3];
    const float* vvec    = (const float*)d_in[4];
    float* out = (float*)d_out;

    const int smemB = 1312 * 16 + (NQMAX * VV + 1792) * 4;  // 85,504 B
    cudaFuncSetAttribute(score_fused_kernel,
                         cudaFuncAttributeMaxDynamicSharedMemorySize, smemB);

    wconv_kernel<<<32, 256>>>(w1, w2);
    proj_tc_kernel<<<144, 256>>>(queries, values);
    score_fused_kernel<<<SCORE_GRID + 1024, 256, smemB>>>(vvec, values);
    av_mma_kernel<<<dim3(HH / 32, QQ / 64, BB), 256>>>(out);
}

// round 9
// speedup vs baseline: 1.6058x; 1.6058x over previous
#include <cuda_runtime.h>
#include <cuda_fp16.h>

#define BB 4
#define QQ 256
#define VV 2048
#define HH 512
#define UU 128

typedef unsigned int       u32;
typedef unsigned long long u64;
typedef unsigned short     u16;

// Scratch (device globals: allocation-free rule)
__device__ float g_pq[BB * QQ * UU];          // [B,Q,U] fp32
__device__ float g_pv[BB * VV * UU];          // [B,V,U] fp32
__device__ u16   g_ah[BB * QQ * VV];          // attn fp16 [B,Q,V]
__device__ u16   g_vth[BB * HH * VV];         // values^T fp16 [B,H,V]
__device__ u16   g_w1thi[UU * HH];            // w1^T hi bf16 [U,H]
__device__ u16   g_w1tlo[UU * HH];
__device__ u16   g_w2thi[UU * HH];            // w2^T hi bf16 [U,H]
__device__ u16   g_w2tlo[UU * HH];

__device__ __forceinline__ float ftanh(float x) {
    float y; asm("tanh.approx.f32 %0, %1;" : "=f"(y) : "f"(x)); return y;
}
__device__ __forceinline__ u16 f2bf(float x) {
    u16 u; asm("cvt.rn.bf16.f32 %0, %1;" : "=h"(u) : "f"(x)); return u;
}
__device__ __forceinline__ float bf2f(u16 u) {
    float f; asm("cvt.f32.bf16 %0, %1;" : "=f"(f) : "h"(u)); return f;
}
__device__ __forceinline__ u32 smem_u32(const void* p) {
    u32 a;
    asm("{ .reg .u64 t; cvta.to.shared.u64 t, %1; cvt.u32.u64 %0, t; }"
        : "=r"(a) : "l"(p));
    return a;
}
__device__ __forceinline__ void ldsm4(u32& r0, u32& r1, u32& r2, u32& r3, u32 a) {
    asm volatile("ldmatrix.sync.aligned.m8n8.x4.shared.b16 {%0,%1,%2,%3}, [%4];"
                 : "=r"(r0), "=r"(r1), "=r"(r2), "=r"(r3) : "r"(a));
}
__device__ __forceinline__ void ldsm2(u32& r0, u32& r1, u32 a) {
    asm volatile("ldmatrix.sync.aligned.m8n8.x2.shared.b16 {%0,%1}, [%2];"
                 : "=r"(r0), "=r"(r1) : "r"(a));
}
// bf16 mma (proj path)
__device__ __forceinline__ void mma_bf(float* d, const u32* a, const u32* b) {
    asm volatile(
        "mma.sync.aligned.m16n8k16.row.col.f32.bf16.bf16.f32 "
        "{%0,%1,%2,%3}, {%4,%5,%6,%7}, {%8,%9}, {%0,%1,%2,%3};"
        : "+f"(d[0]), "+f"(d[1]), "+f"(d[2]), "+f"(d[3])
        : "r"(a[0]), "r"(a[1]), "r"(a[2]), "r"(a[3]), "r"(b[0]), "r"(b[1]));
}
// fp16 mma (av path)
__device__ __forceinline__ void mma_fp(float* d, const u32* a, const u32* b) {
    asm volatile(
        "mma.sync.aligned.m16n8k16.row.col.f32.f16.f16.f32 "
        "{%0,%1,%2,%3}, {%4,%5,%6,%7}, {%8,%9}, {%0,%1,%2,%3};"
        : "+f"(d[0]), "+f"(d[1]), "+f"(d[2]), "+f"(d[3])
        : "r"(a[0]), "r"(a[1]), "r"(a[2]), "r"(a[3]), "r"(b[0]), "r"(b[1]));
}
__device__ __forceinline__ void pack2(float a, float b, u32& h, u32& l) {
    u16 ha = f2bf(a), hb = f2bf(b);
    u16 la = f2bf(a - bf2f(ha)), lb = f2bf(b - bf2f(hb));
    h = (u32)ha | ((u32)hb << 16);
    l = (u32)la | ((u32)lb << 16);
}
__device__ __forceinline__ u32 packh2(float a, float b) {
    __half2 h = __floats2half2_rn(a, b);   // lo=a, hi=b
    return *(u32*)&h;
}

// ---------------------------------------------------------------------------
// Kernel 0: convert.
//   blocks [0,1024):    values 64x64 tiles -> g_vth (transposed, fp16)
//   blocks [1024,1056): w1/w2 64x64 tiles -> bf16 hi/lo transposed
// ---------------------------------------------------------------------------
__global__ __launch_bounds__(256) void convert_kernel(
    const float* __restrict__ values,
    const float* __restrict__ w1, const float* __restrict__ w2)
{
    __shared__ float ts[64 * 65];
    const int bx = blockIdx.x, tid = threadIdx.x;

    if (bx < 1024) {
        const int b = bx >> 8, t = bx & 255;
        const int v0 = (t & 31) * 64, h0 = (t >> 5) * 64;
        const int r = tid >> 2, c0 = tid & 3;
#pragma unroll
        for (int it = 0; it < 4; it++) {
            int c4 = c0 * 4 + it;
            float4 f = ((const float4*)(values + (size_t)(b * VV + v0 + r) * HH + h0))[c4];
            ts[r * 65 + c4 * 4 + 0] = f.x;
            ts[r * 65 + c4 * 4 + 1] = f.y;
            ts[r * 65 + c4 * 4 + 2] = f.z;
            ts[r * 65 + c4 * 4 + 3] = f.w;
        }
        __syncthreads();
        const int hr = tid >> 2, s0 = tid & 3;
#pragma unroll
        for (int it = 0; it < 4; it++) {
            int vs = s0 * 4 + it;
            float f0 = ts[(vs * 4 + 0) * 65 + hr];
            float f1 = ts[(vs * 4 + 1) * 65 + hr];
            float f2 = ts[(vs * 4 + 2) * 65 + hr];
            float f3 = ts[(vs * 4 + 3) * 65 + hr];
            size_t off = (size_t)(b * HH + h0 + hr) * VV + v0 + vs * 4;
            *(uint2*)(g_vth + off) = make_uint2(packh2(f0, f1), packh2(f2, f3));
        }
    } else {
        const int wb = bx - 1024;
        const float* W = (wb < 16) ? w1 : w2;
        u16* dh = (wb < 16) ? g_w1thi : g_w2thi;
        u16* dl = (wb < 16) ? g_w1tlo : g_w2tlo;
        const int t = wb & 15;
        const int h0 = (t & 7) * 64, u0 = (t >> 3) * 64;
        const int r = tid >> 2, c0 = tid & 3;
#pragma unroll
        for (int it = 0; it < 4; it++) {
            int c4 = c0 * 4 + it;
            float4 f = ((const float4*)(W + (size_t)(h0 + r) * UU + u0))[c4];
            ts[r * 65 + c4 * 4 + 0] = f.x;
            ts[r * 65 + c4 * 4 + 1] = f.y;
            ts[r * 65 + c4 * 4 + 2] = f.z;
            ts[r * 65 + c4 * 4 + 3] = f.w;
        }
        __syncthreads();
        const int ur = tid >> 2, s0 = tid & 3;
#pragma unroll
        for (int it = 0; it < 4; it++) {
            int hs = s0 * 4 + it;
            float f0 = ts[(hs * 4 + 0) * 65 + ur];
            float f1 = ts[(hs * 4 + 1) * 65 + ur];
            float f2 = ts[(hs * 4 + 2) * 65 + ur];
            float f3 = ts[(hs * 4 + 3) * 65 + ur];
            u32 h01, l01, h23, l23;
            pack2(f0, f1, h01, l01);
            pack2(f2, f3, h23, l23);
            size_t off = (size_t)(u0 + ur) * HH + h0 + hs * 4;
            *(uint2*)(dh + off) = make_uint2(h01, h23);
            *(uint2*)(dl + off) = make_uint2(l01, l23);
        }
    }
}

// ---------------------------------------------------------------------------
// Kernel A: projections via mma.sync bf16 hi/lo (3 products), static SMEM,
// single-buffer skeleton (store -> prefetch -> sync -> compute -> sync).
// A (values/queries) loaded fp32, converted inline. B = w^T hi/lo.
// CTA tile M=64 x N=128(=U), BK=64, 8 chunks. 8 warps = 2(m)x4(n).
// ---------------------------------------------------------------------------
__global__ __launch_bounds__(256) void proj_tc_kernel(
    const float* __restrict__ queries, const float* __restrict__ values)
{
    __shared__ __align__(16) u16 sAh[64 * 72];
    __shared__ __align__(16) u16 sAl[64 * 72];
    __shared__ __align__(16) u16 sBh[128 * 72];
    __shared__ __align__(16) u16 sBl[128 * 72];

    const int tid = threadIdx.x;
    const int wid = tid >> 5;
    const int lane = tid & 31;
    const int bx = blockIdx.x;

    const float* Afp; const u16 *Bh, *Bl; float* C; int m0;
    if (bx < 128) { Afp = values;  Bh = g_w2thi; Bl = g_w2tlo; C = g_pv; m0 = bx * 64; }
    else          { Afp = queries; Bh = g_w1thi; Bl = g_w1tlo; C = g_pq; m0 = (bx - 128) * 64; }

    const int wm0 = (wid >> 2) * 32;   // 0,32
    const int wn0 = (wid & 3) * 32;    // 0,32,64,96

    const int ar = tid >> 2, ac4 = tid & 3;
    const int br = tid >> 1, bg = tid & 1;

    const float4* gA4 = (const float4*)(Afp + (size_t)m0 * HH);
    const uint4* gBh4 = (const uint4*)Bh;
    const uint4* gBl4 = (const uint4*)Bl;
    const int RWA = HH / 4;
    const int RWB = HH / 8;

    float dacc[2][4][4];
#pragma unroll
    for (int i = 0; i < 2; i++)
#pragma unroll
        for (int j = 0; j < 4; j++)
#pragma unroll
            for (int c = 0; c < 4; c++) dacc[i][j][c] = 0.f;

    float4 pA[4];
    uint4 pBh[4], pBl[4];
#pragma unroll
    for (int it = 0; it < 4; it++)
        pA[it] = gA4[(size_t)ar * RWA + ac4 * 4 + it];
#pragma unroll
    for (int j = 0; j < 4; j++) {
        pBh[j] = gBh4[(size_t)br * RWB + bg * 4 + j];
        pBl[j] = gBl4[(size_t)br * RWB + bg * 4 + j];
    }

    const u32 bAh = smem_u32(sAh), bAl = smem_u32(sAl);
    const u32 bBh = smem_u32(sBh), bBl = smem_u32(sBl);

    const int arow = wm0 + (lane & 15);
    const u32 aoff = (u32)(arow * 9 + (lane >> 4)) * 16;
    const int brow = wn0 + (lane & 7);
    const u32 boff = (u32)(brow * 9 + ((lane >> 3) & 1)) * 16;

    const int NCH = HH / 64;   // 8

    for (int c = 0; c < NCH; c++) {
#pragma unroll
        for (int it = 0; it < 4; it++) {
            u32 h01, l01, h23, l23;
            pack2(pA[it].x, pA[it].y, h01, l01);
            pack2(pA[it].z, pA[it].w, h23, l23);
            u32 s = (u32)(ar * 72 + (ac4 * 4 + it) * 4);
            *(uint2*)(sAh + s) = make_uint2(h01, h23);
            *(uint2*)(sAl + s) = make_uint2(l01, l23);
        }
#pragma unroll
        for (int j = 0; j < 4; j++) {
            u32 s = (u32)(br * 72 + (bg * 4 + j) * 8);
            *(uint4*)(sBh + s) = pBh[j];
            *(uint4*)(sBl + s) = pBl[j];
        }
        if (c + 1 < NCH) {
            int fa = (c + 1) * 16, fb = (c + 1) * 8;
#pragma unroll
            for (int it = 0; it < 4; it++)
                pA[it] = gA4[(size_t)ar * RWA + fa + ac4 * 4 + it];
#pragma unroll
            for (int j = 0; j < 4; j++) {
                pBh[j] = gBh4[(size_t)br * RWB + fb + bg * 4 + j];
                pBl[j] = gBl4[(size_t)br * RWB + fb + bg * 4 + j];
            }
        }
        __syncthreads();

#pragma unroll
        for (int kb = 0; kb < 4; kb++) {
            u32 kadd = (u32)(kb * 2) * 16;
            u32 ah[2][4], al[2][4], bh[4][2], bl[4][2];
#pragma unroll
            for (int mf = 0; mf < 2; mf++) {
                u32 ad = (u32)(mf * 16 * 9) * 16 + aoff + kadd;
                ldsm4(ah[mf][0], ah[mf][1], ah[mf][2], ah[mf][3], bAh + ad);
                ldsm4(al[mf][0], al[mf][1], al[mf][2], al[mf][3], bAl + ad);
            }
#pragma unroll
            for (int nf = 0; nf < 4; nf++) {
                u32 bd = (u32)(nf * 8 * 9) * 16 + boff + kadd;
                ldsm2(bh[nf][0], bh[nf][1], bBh + bd);
                ldsm2(bl[nf][0], bl[nf][1], bBl + bd);
            }
#pragma unroll
            for (int mf = 0; mf < 2; mf++)
#pragma unroll
                for (int nf = 0; nf < 4; nf++)
                    mma_bf(dacc[mf][nf], ah[mf], bh[nf]);
#pragma unroll
            for (int mf = 0; mf < 2; mf++)
#pragma unroll
                for (int nf = 0; nf < 4; nf++)
                    mma_bf(dacc[mf][nf], ah[mf], bl[nf]);
#pragma unroll
            for (int mf = 0; mf < 2; mf++)
#pragma unroll
                for (int nf = 0; nf < 4; nf++)
                    mma_bf(dacc[mf][nf], al[mf], bh[nf]);
        }
        __syncthreads();
    }

    const int g = lane >> 2;
    const int t = lane & 3;
#pragma unroll
    for (int mf = 0; mf < 2; mf++)
#pragma unroll
        for (int nf = 0; nf < 4; nf++) {
            int row = m0 + wm0 + mf * 16 + g;
            int col = wn0 + nf * 8 + t * 2;
            float2 v0, v1;
            v0.x = dacc[mf][nf][0]; v0.y = dacc[mf][nf][1];
            v1.x = dacc[mf][nf][2]; v1.y = dacc[mf][nf][3];
            *(float2*)(C + (size_t)row * UU + col) = v0;
            *(float2*)(C + (size_t)(row + 8) * UU + col) = v1;
        }
}

// ---------------------------------------------------------------------------
// Kernel B: scores + softmax -> attn (fp16). Persistent 148 CTAs.
// MUFU.TANH-bound (at floor).
// ---------------------------------------------------------------------------
#define SCORE_GRID 148
#define CPB 37
#define NQMAX 7

__global__ __launch_bounds__(256) void score_kernel(const float* __restrict__ vvec)
{
    extern __shared__ float4 sm4[];
    float4* pvs4 = sm4;                       // 32*33 f4
    float4* pqs4 = sm4 + 1056;                // 224 f4
    float4* vs4  = sm4 + 1056 + 224;          // 32 f4
    float*  scores = (float*)(sm4 + 1312);    // 7*2048 floats
    float*  sp     = scores + NQMAX * VV;     // 1792 floats

    const int tid = threadIdx.x;
    const int b     = blockIdx.x / CPB;
    const int local = blockIdx.x % CPB;
    const int nq = (local < 34) ? 7 : 6;
    const int q0 = (local < 34) ? local * 7 : 238 + (local - 34) * 6;

    {
        const float4* pqg4 = (const float4*)(g_pq + (size_t)(b * QQ + q0) * UU);
        if (tid < nq * 32) pqs4[tid] = pqg4[tid];
        if (tid < 32) vs4[tid] = ((const float4*)vvec)[tid];
    }

    const float4* pv4 = (const float4*)g_pv;
    const int r  = tid & 31;
    const int ug = tid >> 5;
    const int lrr = tid >> 5;
    const int lc  = tid & 31;

    float4 pf[4];
#pragma unroll
    for (int i = 0; i < 4; i++)
        pf[i] = pv4[(size_t)(b * VV + lrr + i * 8) * 32 + lc];

    __syncthreads();

    float4 vw[4];
#pragma unroll
    for (int u4 = 0; u4 < 4; u4++) vw[u4] = vs4[ug * 4 + u4];

    for (int vt = 0; vt < VV; vt += 32) {
#pragma unroll
        for (int i = 0; i < 4; i++)
            pvs4[(lrr + i * 8) * 33 + lc] = pf[i];
        if (vt + 32 < VV) {
#pragma unroll
            for (int i = 0; i < 4; i++)
                pf[i] = pv4[(size_t)(b * VV + vt + 32 + lrr + i * 8) * 32 + lc];
        }
        __syncthreads();

        float acc[NQMAX];
#pragma unroll
        for (int q = 0; q < NQMAX; q++) acc[q] = 0.f;

        const float4* prow = pvs4 + r * 33 + ug * 4;
#pragma unroll
        for (int u4 = 0; u4 < 4; u4++) {
            float4 p = prow[u4];
            float4 w = vw[u4];
#pragma unroll
            for (int q = 0; q < NQMAX; q++) {
                float4 qv = pqs4[q * 32 + ug * 4 + u4];
                acc[q] += ftanh(qv.x + p.x) * w.x;
                acc[q] += ftanh(qv.y + p.y) * w.y;
                acc[q] += ftanh(qv.z + p.z) * w.z;
                acc[q] += ftanh(qv.w + p.w) * w.w;
            }
        }
#pragma unroll
        for (int q = 0; q < NQMAX; q++) sp[q * 256 + tid] = acc[q];
        __syncthreads();

        if (tid < 224) {
            int q = tid >> 5, rr = tid & 31;
            float s = 0.f;
#pragma unroll
            for (int u = 0; u < 8; u++) s += sp[q * 256 + u * 32 + rr];
            scores[q * VV + vt + rr] = s;
        }
        __syncthreads();
    }

    float* red = sp;
    for (int qi = 0; qi < nq; qi++) {
        float* sc = scores + qi * VV;

        float m = -1e30f;
        for (int i = tid; i < VV; i += 256) m = fmaxf(m, sc[i]);
        red[tid] = m;
        __syncthreads();
        for (int s = 128; s > 0; s >>= 1) {
            if (tid < s) red[tid] = fmaxf(red[tid], red[tid + s]);
            __syncthreads();
        }
        m = red[0];
        __syncthreads();

        float lsum = 0.f;
        for (int i = tid; i < VV; i += 256) {
            float e = __expf(sc[i] - m);
            sc[i] = e;
            lsum += e;
        }
        red[tid] = lsum;
        __syncthreads();
        for (int s = 128; s > 0; s >>= 1) {
            if (tid < s) red[tid] += red[tid + s];
            __syncthreads();
        }
        float inv = 1.f / red[0];
        __syncthreads();

        size_t rowoff = (size_t)(b * QQ + q0 + qi) * VV;
        const float4* sc4 = (const float4*)sc;
        for (int i = tid; i < VV / 4; i += 256) {
            float4 e = sc4[i];
            *(uint2*)(g_ah + rowoff + i * 4) =
                make_uint2(packh2(e.x * inv, e.y * inv), packh2(e.z * inv, e.w * inv));
        }
        __syncthreads();
    }
}

// ---------------------------------------------------------------------------
// Kernel C: out[b] = attn[b] @ values[b] via mma.sync fp16, SINGLE product.
// CTA tile M=64 x N=64, BK=64, 32 chunks. 8 warps = 2(m)x4(n); warp 32x16.
// ---------------------------------------------------------------------------
__global__ __launch_bounds__(256) void av_mma_kernel(float* __restrict__ out)
{
    __shared__ __align__(16) u16 sA[64 * 72];
    __shared__ __align__(16) u16 sB[64 * 72];

    const int tid = threadIdx.x;
    const int wid = tid >> 5;
    const int lane = tid & 31;

    const int b  = blockIdx.z;
    const int m0 = blockIdx.y * 64;
    const int n0 = blockIdx.x * 64;

    const int wm0 = (wid >> 2) * 32;
    const int wn0 = (wid & 3) * 16;

    const int lrow = tid >> 3;
    const int lg   = tid & 7;

    const uint4* gA = (const uint4*)(g_ah + (size_t)(b * QQ + m0) * VV);
    const uint4* gB = (const uint4*)(g_vth + (size_t)(b * HH + n0) * VV);
    const int RW = VV / 8;

    float dacc[2][2][4];
#pragma unroll
    for (int i = 0; i < 2; i++)
#pragma unroll
        for (int j = 0; j < 2; j++)
#pragma unroll
            for (int c = 0; c < 4; c++) dacc[i][j][c] = 0.f;

    uint4 pA[2], pB[2];
#pragma unroll
    for (int i = 0; i < 2; i++) {
        int row = lrow + i * 32;
        pA[i] = gA[(size_t)row * RW + lg];
        pB[i] = gB[(size_t)row * RW + lg];
    }

    const u32 bA = smem_u32(sA), bB = smem_u32(sB);

    const int arow = wm0 + (lane & 15);
    const u32 aoff = (u32)(arow * 9 + (lane >> 4)) * 16;
    const int brow = wn0 + (lane & 7);
    const u32 boff = (u32)(brow * 9 + ((lane >> 3) & 1)) * 16;

    const int NCH = VV / 64;   // 32

    for (int c = 0; c < NCH; c++) {
#pragma unroll
        for (int i = 0; i < 2; i++) {
            int row = lrow + i * 32;
            u32 s = (u32)(row * 9 + lg) * 8;
            *(uint4*)(sA + s) = pA[i];
            *(uint4*)(sB + s) = pB[i];
        }
        if (c + 1 < NCH) {
            int g0 = (c + 1) * 8;
#pragma unroll
            for (int i = 0; i < 2; i++) {
                int row = lrow + i * 32;
                pA[i] = gA[(size_t)row * RW + g0 + lg];
                pB[i] = gB[(size_t)row * RW + g0 + lg];
            }
        }
        __syncthreads();

#pragma unroll
        for (int kb = 0; kb < 4; kb++) {
            u32 kadd = (u32)(kb * 2) * 16;
            u32 a[2][4], bb[2][2];
#pragma unroll
            for (int mf = 0; mf < 2; mf++) {
                u32 ad = (u32)(mf * 16 * 9) * 16 + aoff + kadd;
                ldsm4(a[mf][0], a[mf][1], a[mf][2], a[mf][3], bA + ad);
            }
#pragma unroll
            for (int nf = 0; nf < 2; nf++) {
                u32 bd = (u32)(nf * 8 * 9) * 16 + boff + kadd;
                ldsm2(bb[nf][0], bb[nf][1], bB + bd);
            }
#pragma unroll
            for (int mf = 0; mf < 2; mf++)
#pragma unroll
                for (int nf = 0; nf < 2; nf++)
                    mma_fp(dacc[mf][nf], a[mf], bb[nf]);
        }
        __syncthreads();
    }

    const int g = lane >> 2;
    const int t = lane & 3;
#pragma unroll
    for (int mf = 0; mf < 2; mf++)
#pragma unroll
        for (int nf = 0; nf < 2; nf++) {
            int row = m0 + wm0 + mf * 16 + g;
            int col = n0 + wn0 + nf * 8 + t * 2;
            float2 v0, v1;
            v0.x = dacc[mf][nf][0]; v0.y = dacc[mf][nf][1];
            v1.x = dacc[mf][nf][2]; v1.y = dacc[mf][nf][3];
            *(float2*)(out + (size_t)(b * QQ + row) * HH + col) = v0;
            *(float2*)(out + (size_t)(b * QQ + row + 8) * HH + col) = v1;
        }
}

// ---------------------------------------------------------------------------
extern "C" void kernel_launch(void* const* d_in, const int* in_sizes, int n_in,
                              void* d_out, int out_size)
{
    const float* queries = (const float*)d_in[0];
    const float* values  = (const float*)d_in[1];
    const float* w1      = (const float*)d_in[2];
    const float* w2      = (const float*)d_in[3];
    const float* vvec    = (const float*)d_in[4];
    float* out = (float*)d_out;

    const int smemB = 1312 * 16 + (NQMAX * VV + 1792) * 4;  // 85,504 B
    cudaFuncSetAttribute(score_kernel,
                         cudaFuncAttributeMaxDynamicSharedMemorySize, smemB);

    convert_kernel<<<1056, 256>>>(values, w1, w2);
    proj_tc_kernel<<<144, 256>>>(queries, values);
    score_kernel<<<SCORE_GRID, 256, smemB>>>(vvec);
    av_mma_kernel<<<dim3(HH / 64, QQ / 64, BB), 256>>>(out);
}